// round 1
// baseline (speedup 1.0000x reference)
#include <cuda_runtime.h>
#include <math.h>

#define B_  2
#define S_  2048
#define D_  1024
#define H_  16
#define DH_ 64
#define M_  (B_*S_)   /* 4096 */

// ---- scratch (static device allocations; no cudaMalloc allowed) ----
__device__ float g_q [M_*D_];
__device__ float g_k [M_*D_];
__device__ float g_v [M_*D_];
__device__ float g_g [M_*D_];
__device__ float g_ao[M_*D_];

// ============================================================================
// GEMM: C[M,N] = A[M,K] @ W[N,K]^T   (torch Linear semantics)
// 128x128 block tile, BK=16, 256 threads, 8x8 per thread, float4 everywhere.
// M=4096, N=1024, K=1024 — all tile-divisible, no bounds checks.
// ============================================================================
__device__ __forceinline__ void gemm_body(const float* __restrict__ A,
                                          const float* __restrict__ W,
                                          float* __restrict__ C)
{
    const int K = D_;
    __shared__ float As[16][128];
    __shared__ float Bs[16][128];

    const int tid = threadIdx.x;
    const int tx  = tid & 15;
    const int ty  = tid >> 4;

    const float* Ab = A + (size_t)blockIdx.y * 128 * K;
    const float* Wb = W + (size_t)blockIdx.x * 128 * K;

    float acc[8][8];
    #pragma unroll
    for (int i = 0; i < 8; i++)
        #pragma unroll
        for (int j = 0; j < 8; j++) acc[i][j] = 0.f;

    for (int k0 = 0; k0 < K; k0 += 16) {
        #pragma unroll
        for (int i = 0; i < 2; i++) {
            int idx = tid + i * 256;          // 0..511
            int r   = idx >> 2;               // row 0..127
            int c   = (idx & 3) << 2;         // kcol 0,4,8,12
            float4 a = *(const float4*)(Ab + (size_t)r * K + k0 + c);
            As[c+0][r] = a.x; As[c+1][r] = a.y; As[c+2][r] = a.z; As[c+3][r] = a.w;
            float4 b = *(const float4*)(Wb + (size_t)r * K + k0 + c);
            Bs[c+0][r] = b.x; Bs[c+1][r] = b.y; Bs[c+2][r] = b.z; Bs[c+3][r] = b.w;
        }
        __syncthreads();

        #pragma unroll
        for (int kk = 0; kk < 16; kk++) {
            float4 a0 = *(const float4*)&As[kk][ty * 8];
            float4 a1 = *(const float4*)&As[kk][ty * 8 + 4];
            float4 b0 = *(const float4*)&Bs[kk][tx * 8];
            float4 b1 = *(const float4*)&Bs[kk][tx * 8 + 4];
            float ra[8] = {a0.x,a0.y,a0.z,a0.w,a1.x,a1.y,a1.z,a1.w};
            float rb[8] = {b0.x,b0.y,b0.z,b0.w,b1.x,b1.y,b1.z,b1.w};
            #pragma unroll
            for (int i = 0; i < 8; i++)
                #pragma unroll
                for (int j = 0; j < 8; j++)
                    acc[i][j] += ra[i] * rb[j];
        }
        __syncthreads();
    }

    #pragma unroll
    for (int i = 0; i < 8; i++) {
        float* Cr = C + (size_t)(blockIdx.y * 128 + ty * 8 + i) * D_
                      + blockIdx.x * 128 + tx * 8;
        *(float4*)(Cr)     = make_float4(acc[i][0], acc[i][1], acc[i][2], acc[i][3]);
        *(float4*)(Cr + 4) = make_float4(acc[i][4], acc[i][5], acc[i][6], acc[i][7]);
    }
}

// fused Q/K/V/G projection: blockIdx.z selects the weight + destination
__global__ __launch_bounds__(256)
void gemm_qkvg(const float* __restrict__ X,
               const float* __restrict__ Wq, const float* __restrict__ Wk,
               const float* __restrict__ Wv, const float* __restrict__ Wg)
{
    const float* W;
    float* C;
    switch (blockIdx.z) {
        case 0:  W = Wq; C = g_q; break;
        case 1:  W = Wk; C = g_k; break;
        case 2:  W = Wv; C = g_v; break;
        default: W = Wg; C = g_g; break;
    }
    gemm_body(X, W, C);
}

__global__ __launch_bounds__(256)
void gemm_out(const float* __restrict__ Wo, float* __restrict__ C)
{
    gemm_body(g_ao, Wo, C);
}

// ============================================================================
// RoPE applied in-place to q and k. One thread per (bs, h, j<32) pair.
// ============================================================================
__global__ void rope_kernel()
{
    int i = blockIdx.x * blockDim.x + threadIdx.x;
    if (i >= M_ * H_ * 32) return;
    int j  = i & 31;
    int h  = (i >> 5) & (H_ - 1);
    int bs = i >> 9;
    int s  = bs & (S_ - 1);

    // inv_freq = 10000^{-j/32} = 2^{-j * log2(10000)/32}
    float inv = exp2f(-(float)j * 0.41524101186092029f);
    float ang = (float)s * inv;
    float sn, cs;
    sincosf(ang, &sn, &cs);

    int base = bs * D_ + h * DH_ + j;
    float q1 = g_q[base], q2 = g_q[base + 32];
    g_q[base]      = q1 * cs - q2 * sn;
    g_q[base + 32] = q2 * cs + q1 * sn;
    float k1 = g_k[base], k2 = g_k[base + 32];
    g_k[base]      = k1 * cs - k2 * sn;
    g_k[base + 32] = k2 * cs + k1 * sn;
}

// ============================================================================
// Fused causal retention: per (b, h, 64-query tile) block.
// Loops key tiles of 32 up to the diagonal; decay fused per-score.
// smem: qs 64x65, ks 32x65, vs 32x68, ss 64x33  (~41 KB)
// ============================================================================
__global__ __launch_bounds__(256)
void attn_kernel()
{
    __shared__ float qs[64][65];
    __shared__ float ks[32][65];
    __shared__ float vs[32][68];
    __shared__ float ss[64][33];

    const int qt  = blockIdx.x;
    const int h   = blockIdx.y;
    const int b   = blockIdx.z;
    const int tid = threadIdx.x;
    const int tx  = tid & 15;
    const int ty  = tid >> 4;

    const float gamma = 1.0f - exp2f(-5.0f - (float)h);
    const float lg    = log2f(gamma);

    const float* qp    = g_q + ((size_t)(b * S_ + qt * 64)) * D_ + h * DH_;
    const float* kbase = g_k + ((size_t)b * S_) * D_ + h * DH_;
    const float* vbase = g_v + ((size_t)b * S_) * D_ + h * DH_;

    // load Q tile: 64 rows x 64 cols = 1024 float4 (4 per thread)
    #pragma unroll
    for (int i = 0; i < 4; i++) {
        int idx = tid + i * 256;
        int r   = idx >> 4;
        int c   = (idx & 15) << 2;
        float4 a = *(const float4*)(qp + (size_t)r * D_ + c);
        qs[r][c] = a.x; qs[r][c+1] = a.y; qs[r][c+2] = a.z; qs[r][c+3] = a.w;
    }

    float oacc[4][4];
    #pragma unroll
    for (int i = 0; i < 4; i++)
        #pragma unroll
        for (int j = 0; j < 4; j++) oacc[i][j] = 0.f;

    const int nkt = 2 * qt + 2;
    __syncthreads();

    for (int kt = 0; kt < nkt; kt++) {
        // load K,V tiles: 32 rows x 64 cols each = 512 float4 (2 per thread)
        #pragma unroll
        for (int i = 0; i < 2; i++) {
            int idx = tid + i * 256;
            int r   = idx >> 4;
            int c   = (idx & 15) << 2;
            size_t off = (size_t)(kt * 32 + r) * D_ + c;
            float4 a = *(const float4*)(kbase + off);
            ks[r][c] = a.x; ks[r][c+1] = a.y; ks[r][c+2] = a.z; ks[r][c+3] = a.w;
            float4 bv = *(const float4*)(vbase + off);
            vs[r][c] = bv.x; vs[r][c+1] = bv.y; vs[r][c+2] = bv.z; vs[r][c+3] = bv.w;
        }
        __syncthreads();

        // S = Q K^T  : thread owns 4 rows x 2 cols of the 64x32 score tile
        float sacc[4][2];
        #pragma unroll
        for (int i = 0; i < 4; i++) { sacc[i][0] = 0.f; sacc[i][1] = 0.f; }

        #pragma unroll
        for (int kk = 0; kk < 64; kk++) {
            float qa[4], kb[2];
            #pragma unroll
            for (int i = 0; i < 4; i++) qa[i] = qs[ty * 4 + i][kk];
            #pragma unroll
            for (int j = 0; j < 2; j++) kb[j] = ks[tx * 2 + j][kk];
            #pragma unroll
            for (int i = 0; i < 4; i++) {
                sacc[i][0] += qa[i] * kb[0];
                sacc[i][1] += qa[i] * kb[1];
            }
        }

        // decay mask + 1/sqrt(Dh), write to smem
        #pragma unroll
        for (int i = 0; i < 4; i++) {
            int qg = qt * 64 + ty * 4 + i;
            #pragma unroll
            for (int j = 0; j < 2; j++) {
                int kg   = kt * 32 + tx * 2 + j;
                int diff = qg - kg;
                float val = 0.f;
                if (diff >= 0)
                    val = sacc[i][j] * 0.125f * exp2f((float)diff * lg);
                ss[ty * 4 + i][tx * 2 + j] = val;
            }
        }
        __syncthreads();

        // O += S_tile @ V_tile : thread owns 4 rows x 4 cols of 64x64 O
        #pragma unroll
        for (int kk = 0; kk < 32; kk++) {
            float4 vr = *(const float4*)&vs[kk][tx * 4];
            float sr[4];
            #pragma unroll
            for (int i = 0; i < 4; i++) sr[i] = ss[ty * 4 + i][kk];
            #pragma unroll
            for (int i = 0; i < 4; i++) {
                oacc[i][0] += sr[i] * vr.x;
                oacc[i][1] += sr[i] * vr.y;
                oacc[i][2] += sr[i] * vr.z;
                oacc[i][3] += sr[i] * vr.w;
            }
        }
        __syncthreads();
    }

    // write O in [B,S,D] layout (head h occupies cols h*64..h*64+63)
    float* op = g_ao + ((size_t)(b * S_ + qt * 64)) * D_ + h * DH_;
    #pragma unroll
    for (int i = 0; i < 4; i++) {
        *(float4*)(op + (size_t)(ty * 4 + i) * D_ + tx * 4) =
            make_float4(oacc[i][0], oacc[i][1], oacc[i][2], oacc[i][3]);
    }
}

// ============================================================================
// y = attn_out * silu(g), in place into g_ao
// ============================================================================
__global__ void gate_kernel()
{
    int i = blockIdx.x * blockDim.x + threadIdx.x;
    if (i < M_ * D_) {
        float gv = g_g[i];
        float sg = 1.f / (1.f + expf(-gv));
        g_ao[i] *= gv * sg;
    }
}

// ============================================================================
extern "C" void kernel_launch(void* const* d_in, const int* in_sizes, int n_in,
                              void* d_out, int out_size)
{
    const float* x  = (const float*)d_in[0];
    const float* wq = (const float*)d_in[1];
    const float* wk = (const float*)d_in[2];
    const float* wv = (const float*)d_in[3];
    const float* wg = (const float*)d_in[4];
    const float* wo = (const float*)d_in[5];
    float* out = (float*)d_out;

    dim3 gproj(D_ / 128, M_ / 128, 4);
    gemm_qkvg<<<gproj, 256>>>(x, wq, wk, wv, wg);

    int nrope = M_ * H_ * 32;
    rope_kernel<<<(nrope + 255) / 256, 256>>>();

    attn_kernel<<<dim3(S_ / 64, H_, B_), 256>>>();

    gate_kernel<<<(M_ * D_ + 255) / 256, 256>>>();

    gemm_out<<<dim3(D_ / 128, M_ / 128), 256>>>(wo, out);
}

// round 3
// speedup vs baseline: 2.7282x; 2.7282x over previous
#include <cuda_runtime.h>
#include <stdint.h>
#include <math.h>

#define B_  2
#define S_  2048
#define D_  1024
#define H_  16
#define DH_ 64
#define M_  (B_*S_)   /* 4096 */

// ---- scratch (static device allocations; no cudaMalloc allowed) ----
__device__ float g_q [M_*D_];
__device__ float g_k [M_*D_];
__device__ float g_v [M_*D_];
__device__ float g_g [M_*D_];
__device__ float g_ao[M_*D_];

// ============================================================================
// helpers: tf32 convert + m16n8k8 tf32 mma
// ============================================================================
__device__ __forceinline__ uint32_t f2tf(float x)
{
    uint32_t r;
    asm("cvt.rna.tf32.f32 %0, %1;" : "=r"(r) : "f"(x));
    return r;
}

__device__ __forceinline__ void mma_tf32(float c[4],
                                         uint32_t a0, uint32_t a1,
                                         uint32_t a2, uint32_t a3,
                                         uint32_t b0, uint32_t b1)
{
    asm volatile(
        "mma.sync.aligned.m16n8k8.row.col.f32.tf32.tf32.f32 "
        "{%0,%1,%2,%3},{%4,%5,%6,%7},{%8,%9},{%0,%1,%2,%3};"
        : "+f"(c[0]), "+f"(c[1]), "+f"(c[2]), "+f"(c[3])
        : "r"(a0), "r"(a1), "r"(a2), "r"(a3), "r"(b0), "r"(b1));
}

// ============================================================================
// TF32 GEMM: C[M,N] = A[M,K] @ W[N,K]^T
// BM=128, BN=128, BK=16, 256 threads (8 warps, 2x4), warp tile 64x32.
// A smem [m][k] pad->20, B smem [n][k] pad->20 : frag LDS conflict-free.
// ============================================================================
#define GPAD 20

__device__ __forceinline__ void gemm_tf32_body(const float* __restrict__ A,
                                               const float* __restrict__ W,
                                               float* __restrict__ C)
{
    __shared__ uint32_t As[2][128][GPAD];
    __shared__ uint32_t Bs[2][128][GPAD];

    const int K    = D_;
    const int tid  = threadIdx.x;
    const int lane = tid & 31;
    const int w    = tid >> 5;
    const int wm   = (w >> 2) * 64;   // 0 or 64
    const int wn   = (w & 3) * 32;    // 0,32,64,96

    const float* Ab = A + (size_t)blockIdx.y * 128 * K;
    const float* Wb = W + (size_t)blockIdx.x * 128 * K;

    const int lm = tid >> 2;          // 0..63
    const int lc = (tid & 3) << 2;    // 0,4,8,12

    float acc[4][4][4];
    #pragma unroll
    for (int i = 0; i < 4; i++)
        #pragma unroll
        for (int j = 0; j < 4; j++)
            #pragma unroll
            for (int r = 0; r < 4; r++) acc[i][j][r] = 0.f;

    // preload tile 0
    float4 va[2], vb[2];
    #pragma unroll
    for (int i = 0; i < 2; i++) {
        va[i] = *(const float4*)(Ab + (size_t)(lm + 64*i) * K + lc);
        vb[i] = *(const float4*)(Wb + (size_t)(lm + 64*i) * K + lc);
    }
    #pragma unroll
    for (int i = 0; i < 2; i++) {
        uint4 ua = make_uint4(f2tf(va[i].x), f2tf(va[i].y), f2tf(va[i].z), f2tf(va[i].w));
        *(uint4*)&As[0][lm + 64*i][lc] = ua;
        uint4 ub = make_uint4(f2tf(vb[i].x), f2tf(vb[i].y), f2tf(vb[i].z), f2tf(vb[i].w));
        *(uint4*)&Bs[0][lm + 64*i][lc] = ub;
    }
    __syncthreads();

    const int NIT = K / 16;   // 64
    for (int it = 0; it < NIT; it++) {
        const int buf = it & 1;

        if (it + 1 < NIT) {
            const int k0 = (it + 1) * 16;
            #pragma unroll
            for (int i = 0; i < 2; i++) {
                va[i] = *(const float4*)(Ab + (size_t)(lm + 64*i) * K + k0 + lc);
                vb[i] = *(const float4*)(Wb + (size_t)(lm + 64*i) * K + k0 + lc);
            }
        }

        #pragma unroll
        for (int ks = 0; ks < 2; ks++) {
            const int kb = ks * 8 + (lane & 3);
            const int ra = lane >> 2;
            uint32_t a[4][4], bfr[4][2];
            #pragma unroll
            for (int mf = 0; mf < 4; mf++) {
                const uint32_t* p = &As[buf][wm + mf*16 + ra][kb];
                a[mf][0] = p[0];        a[mf][2] = p[4];
                a[mf][1] = p[8*GPAD];   a[mf][3] = p[8*GPAD + 4];
            }
            #pragma unroll
            for (int nf = 0; nf < 4; nf++) {
                const uint32_t* p = &Bs[buf][wn + nf*8 + ra][kb];
                bfr[nf][0] = p[0];      bfr[nf][1] = p[4];
            }
            #pragma unroll
            for (int mf = 0; mf < 4; mf++)
                #pragma unroll
                for (int nf = 0; nf < 4; nf++)
                    mma_tf32(acc[mf][nf],
                             a[mf][0], a[mf][1], a[mf][2], a[mf][3],
                             bfr[nf][0], bfr[nf][1]);
        }

        if (it + 1 < NIT) {
            const int nb = buf ^ 1;
            #pragma unroll
            for (int i = 0; i < 2; i++) {
                uint4 ua = make_uint4(f2tf(va[i].x), f2tf(va[i].y), f2tf(va[i].z), f2tf(va[i].w));
                *(uint4*)&As[nb][lm + 64*i][lc] = ua;
                uint4 ub = make_uint4(f2tf(vb[i].x), f2tf(vb[i].y), f2tf(vb[i].z), f2tf(vb[i].w));
                *(uint4*)&Bs[nb][lm + 64*i][lc] = ub;
            }
        }
        __syncthreads();
    }

    // epilogue
    const int rbase = blockIdx.y * 128 + wm + (lane >> 2);
    const int cbase = blockIdx.x * 128 + wn + ((lane & 3) << 1);
    #pragma unroll
    for (int mf = 0; mf < 4; mf++) {
        #pragma unroll
        for (int nf = 0; nf < 4; nf++) {
            float* p0 = C + (size_t)(rbase + mf*16) * D_ + cbase + nf*8;
            *(float2*)p0 = make_float2(acc[mf][nf][0], acc[mf][nf][1]);
            float* p1 = p0 + (size_t)8 * D_;
            *(float2*)p1 = make_float2(acc[mf][nf][2], acc[mf][nf][3]);
        }
    }
}

__global__ __launch_bounds__(256, 2)
void gemm_qkvg(const float* __restrict__ X,
               const float* __restrict__ Wq, const float* __restrict__ Wk,
               const float* __restrict__ Wv, const float* __restrict__ Wg)
{
    const float* W;
    float* C;
    switch (blockIdx.z) {
        case 0:  W = Wq; C = g_q; break;
        case 1:  W = Wk; C = g_k; break;
        case 2:  W = Wv; C = g_v; break;
        default: W = Wg; C = g_g; break;
    }
    gemm_tf32_body(X, W, C);
}

__global__ __launch_bounds__(256, 2)
void gemm_out(const float* __restrict__ Wo, float* __restrict__ C)
{
    gemm_tf32_body(g_ao, Wo, C);
}

// ============================================================================
// RoPE applied in-place to q and k. One thread per (bs, h, j<32) pair.
// ============================================================================
__global__ void rope_kernel()
{
    int i = blockIdx.x * blockDim.x + threadIdx.x;
    if (i >= M_ * H_ * 32) return;
    int j  = i & 31;
    int h  = (i >> 5) & (H_ - 1);
    int bs = i >> 9;
    int s  = bs & (S_ - 1);

    float inv = exp2f(-(float)j * 0.41524101186092029f);
    float ang = (float)s * inv;
    float sn, cs;
    sincosf(ang, &sn, &cs);

    int base = bs * D_ + h * DH_ + j;
    float q1 = g_q[base], q2 = g_q[base + 32];
    g_q[base]      = q1 * cs - q2 * sn;
    g_q[base + 32] = q2 * cs + q1 * sn;
    float k1 = g_k[base], k2 = g_k[base + 32];
    g_k[base]      = k1 * cs - k2 * sn;
    g_k[base + 32] = k2 * cs + k1 * sn;
}

// ============================================================================
// Fused causal retention, TF32 mma. Block = (qtile64, h, b), 256 threads.
// Key tiles of 32. Decay factorized: gamma^(s-t) = f_tile * gamma^r * gamma^-t.
// Gate (silu) fused into epilogue.
// smem: Qs 64x68, Ks 32x68, Vs 32x68, Ss 64x36 (uint32)  -> 44 KB
// ============================================================================
__global__ __launch_bounds__(256, 2)
void attn_kernel()
{
    __shared__ uint32_t Qs[64][68];
    __shared__ uint32_t Ks[32][68];
    __shared__ uint32_t Vs[32][68];
    __shared__ uint32_t Ss[64][36];

    const int qt   = (int)gridDim.x - 1 - (int)blockIdx.x;  // heavy tiles first
    const int h    = blockIdx.y;
    const int b    = blockIdx.z;
    const int tid  = threadIdx.x;
    const int lane = tid & 31;
    const int w    = tid >> 5;
    const int wm   = (w >> 1) * 16;   // S/O row base
    const int wns  = (w & 1) * 16;    // S col base
    const int wno  = (w & 1) * 32;    // O col base

    const float gamma = 1.0f - exp2f(-5.0f - (float)h);
    const float lg    = log2f(gamma);

    const float* qp = g_q + (size_t)(b * S_ + qt * 64) * D_ + h * DH_;
    const float* kp = g_k + (size_t)(b * S_) * D_ + h * DH_;
    const float* vp = g_v + (size_t)(b * S_) * D_ + h * DH_;

    // load Q tile 64x64 (4 float4 / thread), cvt to tf32
    #pragma unroll
    for (int i = 0; i < 4; i++) {
        int idx = tid + i * 256;
        int r   = idx >> 4;
        int c   = (idx & 15) << 2;
        float4 v = *(const float4*)(qp + (size_t)r * D_ + c);
        *(uint4*)&Qs[r][c] = make_uint4(f2tf(v.x), f2tf(v.y), f2tf(v.z), f2tf(v.w));
    }

    // per-thread decay factors (hoisted out of the key loop)
    const int rloc = wm + (lane >> 2);
    float grow0 = 0.125f * exp2f(lg * (float)rloc);        // gamma^r * 1/sqrt(Dh)
    float grow1 = 0.125f * exp2f(lg * (float)(rloc + 8));
    float gcolv[2][2];
    #pragma unroll
    for (int nf = 0; nf < 2; nf++)
        #pragma unroll
        for (int j = 0; j < 2; j++) {
            int t = wns + nf*8 + ((lane & 3) << 1) + j;
            gcolv[nf][j] = exp2f(-lg * (float)t);          // gamma^-t
        }

    float oacc[4][4];
    #pragma unroll
    for (int i = 0; i < 4; i++)
        #pragma unroll
        for (int j = 0; j < 4; j++) oacc[i][j] = 0.f;

    const int nkt = 2 * qt + 2;
    __syncthreads();

    for (int kt = 0; kt < nkt; kt++) {
        // load K,V tiles 32x64 (2 float4 each / thread), cvt
        #pragma unroll
        for (int i = 0; i < 2; i++) {
            int idx = tid + i * 256;
            int r   = idx >> 4;
            int c   = (idx & 15) << 2;
            size_t off = (size_t)(kt * 32 + r) * D_ + c;
            float4 kv = *(const float4*)(kp + off);
            *(uint4*)&Ks[r][c] = make_uint4(f2tf(kv.x), f2tf(kv.y), f2tf(kv.z), f2tf(kv.w));
            float4 vv = *(const float4*)(vp + off);
            *(uint4*)&Vs[r][c] = make_uint4(f2tf(vv.x), f2tf(vv.y), f2tf(vv.z), f2tf(vv.w));
        }
        __syncthreads();

        // S = Q K^T : warp tile 16x16, 8 k-steps
        float sc[2][4];
        #pragma unroll
        for (int nf = 0; nf < 2; nf++)
            #pragma unroll
            for (int r = 0; r < 4; r++) sc[nf][r] = 0.f;

        #pragma unroll
        for (int ks = 0; ks < 8; ks++) {
            const uint32_t* pa = &Qs[wm + (lane >> 2)][ks*8 + (lane & 3)];
            uint32_t a0 = pa[0],       a2 = pa[4];
            uint32_t a1 = pa[8*68],    a3 = pa[8*68 + 4];
            #pragma unroll
            for (int nf = 0; nf < 2; nf++) {
                const uint32_t* pb = &Ks[wns + nf*8 + (lane >> 2)][ks*8 + (lane & 3)];
                mma_tf32(sc[nf], a0, a1, a2, a3, pb[0], pb[4]);
            }
        }

        // decay + causal mask, write tf32 scores to Ss
        const int   dbase = qt * 64 - kt * 32;
        const float f     = exp2f(lg * (float)dbase);      // gamma^(qbase - ktbase)
        const float fg0   = f * grow0;
        const float fg1   = f * grow1;
        #pragma unroll
        for (int nf = 0; nf < 2; nf++) {
            const int t  = wns + nf*8 + ((lane & 3) << 1);
            const int d0 = dbase + rloc - t;               // diff for (row rloc, col t)
            float v00 = (d0     >= 0) ? sc[nf][0] * fg0 * gcolv[nf][0] : 0.f;
            float v01 = (d0 - 1 >= 0) ? sc[nf][1] * fg0 * gcolv[nf][1] : 0.f;
            float v10 = (d0 + 8 >= 0) ? sc[nf][2] * fg1 * gcolv[nf][0] : 0.f;
            float v11 = (d0 + 7 >= 0) ? sc[nf][3] * fg1 * gcolv[nf][1] : 0.f;
            uint32_t* ps = &Ss[wm + (lane >> 2)][t];
            *(uint2*)ps             = make_uint2(f2tf(v00), f2tf(v01));
            *(uint2*)(ps + 8*36)    = make_uint2(f2tf(v10), f2tf(v11));
        }
        __syncthreads();

        // O += S @ V : warp tile 16x32, 4 k-steps
        #pragma unroll
        for (int ks = 0; ks < 4; ks++) {
            const uint32_t* pa = &Ss[wm + (lane >> 2)][ks*8 + (lane & 3)];
            uint32_t a0 = pa[0],       a2 = pa[4];
            uint32_t a1 = pa[8*36],    a3 = pa[8*36 + 4];
            #pragma unroll
            for (int nf = 0; nf < 4; nf++) {
                const uint32_t* pb = &Vs[ks*8 + (lane & 3)][wno + nf*8 + (lane >> 2)];
                mma_tf32(oacc[nf], a0, a1, a2, a3, pb[0], pb[4*68]);
            }
        }
        __syncthreads();
    }

    // epilogue: out = O * silu(g), written to g_ao
    const size_t rowbase = (size_t)(b * S_ + qt * 64) * D_ + h * DH_;
    const float* gp = g_g + rowbase;
    float*       op = g_ao + rowbase;
    #pragma unroll
    for (int nf = 0; nf < 4; nf++) {
        const int c = wno + nf*8 + ((lane & 3) << 1);
        {
            const size_t o = (size_t)rloc * D_ + c;
            float2 gv = *(const float2*)(gp + o);
            float s0 = gv.x / (1.f + expf(-gv.x));
            float s1 = gv.y / (1.f + expf(-gv.y));
            *(float2*)(op + o) = make_float2(oacc[nf][0] * s0, oacc[nf][1] * s1);
        }
        {
            const size_t o = (size_t)(rloc + 8) * D_ + c;
            float2 gv = *(const float2*)(gp + o);
            float s0 = gv.x / (1.f + expf(-gv.x));
            float s1 = gv.y / (1.f + expf(-gv.y));
            *(float2*)(op + o) = make_float2(oacc[nf][2] * s0, oacc[nf][3] * s1);
        }
    }
}

// ============================================================================
extern "C" void kernel_launch(void* const* d_in, const int* in_sizes, int n_in,
                              void* d_out, int out_size)
{
    const float* x  = (const float*)d_in[0];
    const float* wq = (const float*)d_in[1];
    const float* wk = (const float*)d_in[2];
    const float* wv = (const float*)d_in[3];
    const float* wg = (const float*)d_in[4];
    const float* wo = (const float*)d_in[5];
    float* out = (float*)d_out;

    dim3 gproj(D_ / 128, M_ / 128, 4);
    gemm_qkvg<<<gproj, 256>>>(x, wq, wk, wv, wg);

    int nrope = M_ * H_ * 32;
    rope_kernel<<<(nrope + 255) / 256, 256>>>();

    attn_kernel<<<dim3(S_ / 64, H_, B_), 256>>>();

    gemm_out<<<dim3(D_ / 128, M_ / 128), 256>>>(wo, out);
}